// round 15
// baseline (speedup 1.0000x reference)
#include <cuda_runtime.h>
#include <cuda_fp16.h>
#include <math.h>
#include <stdint.h>

#define TT   1024
#define DIN  128
#define HH   512
#define DOUT 128
#define NG   16
#define NS   8
#define NTHR 512

// smem byte offsets
#define SM_W   0                        // [40 kt][4 ng][32 lane][16B] = 81920 B
#define SM_A   81920                    // [32 kt][2 mt][32 lane][16B] = 32768 B
#define SM_RED (SM_A + 32768)           // [8 wid'][32 lane][8 f] = 8192 B
#define SM_BIAS (SM_RED + 8192)         // 64 floats
#define SMEM_TOTAL (SM_BIAS + 256)

// fragment-order fp16 globals
__device__ uint32_t g_Wf[40 * 64 * 32 * 2];                    // B frags (W), 640KB
__device__ uint32_t g_xf[(size_t)NG * TT * 8 * 2 * 32 * 4];    // A frags (x), 128MB
__device__ uint32_t g_hf[2][NG * 32 * 2 * 32 * 4];             // A frags (h), 2x512KB
__device__ unsigned g_flag[NG][NS][32];

// ---- prep: W -> B fragments.  B[k][n] = W[j=n][k] ----
__global__ void prep_w(const float* __restrict__ Wh, const float* __restrict__ Wx) {
    int i = blockIdx.x * blockDim.x + threadIdx.x;   // one b32 (2 fp16)
    if (i >= 40 * 64 * 32 * 2) return;
    int breg = i & 1;
    int lane = (i >> 1) & 31;
    int nt   = (i >> 6) & 63;
    int kt   = i >> 12;                  // 0..39 (0..31 = Wh, 32..39 = Wx)
    int j  = nt * 8 + (lane >> 2);
    int k2 = kt * 16 + 2 * (lane & 3) + 8 * breg;
    float v0, v1;
    if (kt < 32) { v0 = Wh[(size_t)j * HH + k2];        v1 = Wh[(size_t)j * HH + k2 + 1]; }
    else         { v0 = Wx[(size_t)j * DIN + (k2-512)]; v1 = Wx[(size_t)j * DIN + (k2-512) + 1]; }
    __half2 h = __floats2half2_rn(v0, v1);
    g_Wf[i] = *reinterpret_cast<uint32_t*>(&h);
}

// ---- prep: x -> A fragments (one-time) ----
__global__ void prep_x(const float* __restrict__ x) {
    size_t i = (size_t)blockIdx.x * blockDim.x + threadIdx.x;  // 8,388,608 lane-entries
    int lane = (int)(i & 31);
    int mt   = (int)((i >> 5) & 1);
    int kt   = (int)((i >> 6) & 7);
    int t    = (int)((i >> 9) & 1023);
    int g    = (int)(i >> 19);
    int r = mt * 16 + (lane >> 2);
    int k = kt * 16 + 2 * (lane & 3);
    uint32_t w[4];
    #pragma unroll
    for (int a = 0; a < 4; ++a) {
        int i_hi = a >> 1, i_r8 = a & 1;
        int b  = g * 32 + r + 8 * i_r8;
        int kk = k + 8 * i_hi;
        const float* p = &x[((size_t)b * TT + t) * DIN + kk];
        __half2 h = __floats2half2_rn(p[0], p[1]);
        w[a] = *reinterpret_cast<uint32_t*>(&h);
    }
    *reinterpret_cast<uint4*>(&g_xf[i * 4]) = make_uint4(w[0], w[1], w[2], w[3]);
}

__global__ void zero_kernel() {
    int i = blockIdx.x * blockDim.x + threadIdx.x;
    int stride = gridDim.x * blockDim.x;
    for (int k = i; k < NG * 32 * 2 * 32 * 4; k += stride) g_hf[0][k] = 0u;
    unsigned* f = &g_flag[0][0][0];
    for (int k = i; k < NG * NS * 32; k += stride) f[k] = 0u;
}

#define MMA(AC, A0, A1, A2, A3, B0, B1)                                        \
    asm volatile(                                                              \
        "mma.sync.aligned.m16n8k16.row.col.f32.f16.f16.f32 "                   \
        "{%0,%1,%2,%3}, {%4,%5,%6,%7}, {%8,%9}, {%0,%1,%2,%3};"                \
        : "+f"((AC)[0]), "+f"((AC)[1]), "+f"((AC)[2]), "+f"((AC)[3])           \
        : "r"(A0), "r"(A1), "r"(A2), "r"(A3), "r"(B0), "r"(B1))

#define LDS128(R0, R1, R2, R3, ADDR)                                           \
    asm volatile("ld.shared.v4.u32 {%0,%1,%2,%3}, [%4];"                       \
        : "=r"(R0), "=r"(R1), "=r"(R2), "=r"(R3) : "r"(ADDR))

__global__ __launch_bounds__(NTHR, 1) void scan_kernel(
    const float* __restrict__ bx,
    const float* __restrict__ bh)
{
    extern __shared__ char smem[];
    const uint32_t sb = (uint32_t)__cvta_generic_to_shared(smem);
    float* bias_s = reinterpret_cast<float*>(smem + SM_BIAS);

    const int tid  = threadIdx.x;
    const int lane = tid & 31;
    const int wid  = tid >> 5;
    const int g    = blockIdx.x >> 3;
    const int s    = blockIdx.x & 7;
    // wid = kh*8 + ng*2 + mt
    const int kh   = wid >> 3;           // k-half 0/1
    const int ng   = (wid >> 1) & 3;     // n-pair
    const int mt_w = wid & 1;            // m-tile

    // ---- load W fragments, repacked ng-paired: [kt][ng][lane][b0..b3] ----
    {
        const uint2* src = reinterpret_cast<const uint2*>(g_Wf);
        uint4* dst = reinterpret_cast<uint4*>(smem + SM_W);
        for (int i = tid; i < 40 * 4 * 32; i += NTHR) {
            int ln = i & 31, gg = (i >> 5) & 3, kt = i >> 7;
            uint2 a = src[(size_t)(kt * 64 + s * 8 + 2 * gg) * 32 + ln];
            uint2 b = src[(size_t)(kt * 64 + s * 8 + 2 * gg + 1) * 32 + ln];
            dst[i] = make_uint4(a.x, a.y, b.x, b.y);
        }
    }
    if (tid < 64) bias_s[tid] = bx[s * 64 + tid] + bh[s * 64 + tid];
    __syncthreads();

    // x fragments in registers: warp's mt, its 4 x-kts (32+kh*4 ..)
    uint4 xr[4];
    #pragma unroll
    for (int i = 0; i < 4; ++i)
        xr[i] = __ldg(reinterpret_cast<const uint4*>(g_xf) +
                      (size_t)((((g * TT + 0) * 8 + kh * 4 + i) * 2 + mt_w) * 32 + lane));

    const uint32_t abase = sb + SM_A + mt_w * 512 + lane * 16;
    const uint32_t bbase = sb + SM_W + ng * 512 + lane * 16;
    float* redv = reinterpret_cast<float*>(smem + SM_RED);
    const int rw = ng * 2 + mt_w;                 // 0..7 reduction slot

    for (int t = 0; t < TT; ++t) {
        const int pr = t & 1, pw = pr ^ 1;
        float a0A[4] = {0,0,0,0}, a0B[4] = {0,0,0,0};
        float a1A[4] = {0,0,0,0}, a1B[4] = {0,0,0,0};

        // ---- x MMAs from registers (B kt 32+kh*4 .. +3) — before peer wait ----
        #pragma unroll
        for (int i = 0; i < 4; ++i) {
            uint32_t b0, b1, b2, b3;
            LDS128(b0, b1, b2, b3, bbase + (32 + kh * 4 + i) * 2048);
            float* A0 = (i & 1) ? a0B : a0A;
            float* A1 = (i & 1) ? a1B : a1A;
            MMA(A0, xr[i].x, xr[i].y, xr[i].z, xr[i].w, b0, b1);
            MMA(A1, xr[i].x, xr[i].y, xr[i].z, xr[i].w, b2, b3);
        }
        // prefetch x(t+1)
        {
            const int tn = (t + 1 < TT) ? t + 1 : TT - 1;
            #pragma unroll
            for (int i = 0; i < 4; ++i)
                xr[i] = __ldg(reinterpret_cast<const uint4*>(g_xf) +
                              (size_t)((((g * TT + tn) * 8 + kh * 4 + i) * 2 + mt_w) * 32 + lane));
        }

        // ---- wait peers: h_t published ----
        if (tid < NS) {
            unsigned v;
            do {
                asm volatile("ld.acquire.gpu.global.u32 %0, [%1];"
                             : "=r"(v) : "l"(&g_flag[g][tid][0]));
            } while (v < (unsigned)t);
        }
        __syncthreads();

        // ---- single-shot h stage: 32 KB contiguous copy ----
        {
            const uint4* src = reinterpret_cast<const uint4*>(&g_hf[pr][(size_t)g * 8192]);
            uint4* dst = reinterpret_cast<uint4*>(smem + SM_A);
            uint4 p0 = __ldcg(src + tid);
            uint4 p1 = __ldcg(src + 512 + tid);
            uint4 p2 = __ldcg(src + 1024 + tid);
            uint4 p3 = __ldcg(src + 1536 + tid);
            dst[tid] = p0; dst[512 + tid] = p1;
            dst[1024 + tid] = p2; dst[1536 + tid] = p3;
        }
        __syncthreads();

        // ---- h MMAs: 16 kt for this k-half, banked by parity ----
        #pragma unroll
        for (int i = 0; i < 16; ++i) {
            const int kt = kh * 16 + i;
            uint32_t A0, A1, A2, A3, b0, b1, b2, b3;
            LDS128(A0, A1, A2, A3, abase + kt * 1024);
            LDS128(b0, b1, b2, b3, bbase + kt * 2048);
            float* c0 = (i & 1) ? a0B : a0A;
            float* c1 = (i & 1) ? a1B : a1A;
            MMA(c0, A0, A1, A2, A3, b0, b1);
            MMA(c1, A0, A1, A2, A3, b2, b3);
        }

        // merge banks
        float acc0[4], acc1[4];
        #pragma unroll
        for (int i = 0; i < 4; ++i) { acc0[i] = a0A[i] + a0B[i]; acc1[i] = a1A[i] + a1B[i]; }

        // ---- cross-warp k reduction: kh1 dumps, kh0 finalizes ----
        if (kh == 1) {
            float* rp = &redv[(rw * 32 + lane) * 8];
            *reinterpret_cast<float4*>(rp)     = make_float4(acc0[0], acc0[1], acc0[2], acc0[3]);
            *reinterpret_cast<float4*>(rp + 4) = make_float4(acc1[0], acc1[1], acc1[2], acc1[3]);
        }
        __syncthreads();
        if (kh == 0) {
            const float* rp = &redv[(rw * 32 + lane) * 8];
            float4 r0 = *reinterpret_cast<const float4*>(rp);
            float4 r1 = *reinterpret_cast<const float4*>(rp + 4);
            acc0[0] += r0.x; acc0[1] += r0.y; acc0[2] += r0.z; acc0[3] += r0.w;
            acc1[0] += r1.x; acc1[1] += r1.y; acc1[2] += r1.z; acc1[3] += r1.w;

            // ---- epilogue: bias + tanh, pack fp16x2, publish fragment layout ----
            uint32_t* hdst = &g_hf[pw][0];
            #pragma unroll
            for (int tile = 0; tile < 2; ++tile) {
                const float* ac = tile ? acc1 : acc0;
                const int ntl = 2 * ng + tile;
                const int jl  = ntl * 8 + 2 * (lane & 3);
                const float bf0 = bias_s[jl], bf1 = bias_s[jl + 1];
                const int kt = s * 4 + (ntl >> 1);
                #pragma unroll
                for (int ir = 0; ir < 2; ++ir) {
                    float h0 = tanhf(ac[2 * ir + 0] + bf0);
                    float h1 = tanhf(ac[2 * ir + 1] + bf1);
                    __half2 hh = __floats2half2_rn(h0, h1);
                    int a = 2 * (ntl & 1) + ir;
                    __stcg(&hdst[((g * 32 + kt) * 2 + mt_w) * 128 + lane * 4 + a],
                           *reinterpret_cast<uint32_t*>(&hh));
                }
            }
        }

        // ---- cross-CTA step barrier ----
        __syncthreads();
        if (tid == 0) {
            asm volatile("fence.acq_rel.gpu;" ::: "memory");
            asm volatile("st.release.gpu.global.u32 [%0], %1;"
                         :: "l"(&g_flag[g][s][0]), "r"((unsigned)(t + 1))
                         : "memory");
        }
    }
}

// y[b][o] = by[o] + sum_k h_T[b][k] * Wy[o][k] ; h_T fragments in g_hf[0]
__global__ __launch_bounds__(128, 1) void y_kernel(
    const float* __restrict__ Wy,
    const float* __restrict__ by,
    float* __restrict__ y)
{
    __shared__ float hs[HH];
    const int b = blockIdx.x, o = threadIdx.x;
    const int g = b >> 5, m = b & 31, mt = m >> 4;
    const uint32_t* hf = &g_hf[0][0];
    #pragma unroll
    for (int w = 0; w < 2; ++w) {
        int k  = o * 4 + w * 2;
        int kt = k >> 4, kl = k & 15;
        int lane = ((m & 7) << 2) | ((kl & 7) >> 1);
        int a = 2 * (kl >> 3) + ((m >> 3) & 1);
        uint32_t word = hf[((g * 32 + kt) * 2 + mt) * 128 + lane * 4 + a];
        __half2 hh = *reinterpret_cast<__half2*>(&word);
        hs[k]     = __low2float(hh);
        hs[k + 1] = __high2float(hh);
    }
    __syncthreads();
    const float4* w4 = reinterpret_cast<const float4*>(&Wy[(size_t)o * HH]);
    float acc = by[o];
    #pragma unroll 8
    for (int q = 0; q < HH / 4; ++q) {
        float4 w = __ldg(&w4[q]);
        acc = fmaf(w.x, hs[4 * q + 0], acc);
        acc = fmaf(w.y, hs[4 * q + 1], acc);
        acc = fmaf(w.z, hs[4 * q + 2], acc);
        acc = fmaf(w.w, hs[4 * q + 3], acc);
    }
    y[(size_t)b * DOUT + o] = acc;
}

extern "C" void kernel_launch(void* const* d_in, const int* in_sizes, int n_in,
                              void* d_out, int out_size) {
    const float* x  = (const float*)d_in[0];
    const float* Wx = (const float*)d_in[1];
    const float* bx = (const float*)d_in[2];
    const float* Wh = (const float*)d_in[3];
    const float* bh = (const float*)d_in[4];
    const float* Wy = (const float*)d_in[5];
    const float* by = (const float*)d_in[6];
    float* y = (float*)d_out;

    cudaFuncSetAttribute(scan_kernel,
                         cudaFuncAttributeMaxDynamicSharedMemorySize, SMEM_TOTAL);

    prep_w<<<640, 256>>>(Wh, Wx);
    prep_x<<<32768, 256>>>(x);
    zero_kernel<<<128, 256>>>();
    scan_kernel<<<NG * NS, NTHR, SMEM_TOTAL>>>(bx, bh);
    y_kernel<<<512, 128>>>(Wy, by, y);
}

// round 16
// speedup vs baseline: 1.5191x; 1.5191x over previous
#include <cuda_runtime.h>
#include <cuda_fp16.h>
#include <math.h>
#include <stdint.h>

#define TT   1024
#define DIN  128
#define HH   512
#define DOUT 128
#define NG   16
#define NS   8
#define NTHR 256

// smem byte offsets
#define SM_W   0                        // [40 kt][4 ng][32 lane][16B] = 81920 B
#define SM_A   81920                    // 2 bufs x [32 kt][2 mt][32 lane][16B] = 65536 B
#define SM_BIAS (SM_A + 65536)          // 64 floats
#define SMEM_TOTAL (SM_BIAS + 256)

// fragment-order fp16 globals
__device__ uint32_t g_Wf[40 * 64 * 32 * 2];                    // B frags (W), 640KB
__device__ uint32_t g_xf[(size_t)NG * TT * 8 * 2 * 32 * 4];    // A frags (x), 128MB
__device__ uint32_t g_hf[2][NG * 32 * 2 * 32 * 4];             // A frags (h), 2x512KB
__device__ unsigned g_flag[NG][NS][32];

// ---- prep: W -> B fragments.  B[k][n] = W[j=n][k] ----
__global__ void prep_w(const float* __restrict__ Wh, const float* __restrict__ Wx) {
    int i = blockIdx.x * blockDim.x + threadIdx.x;   // one b32 (2 fp16)
    if (i >= 40 * 64 * 32 * 2) return;
    int breg = i & 1;
    int lane = (i >> 1) & 31;
    int nt   = (i >> 6) & 63;
    int kt   = i >> 12;                  // 0..39 (0..31 = Wh, 32..39 = Wx)
    int j  = nt * 8 + (lane >> 2);
    int k2 = kt * 16 + 2 * (lane & 3) + 8 * breg;
    float v0, v1;
    if (kt < 32) { v0 = Wh[(size_t)j * HH + k2];        v1 = Wh[(size_t)j * HH + k2 + 1]; }
    else         { v0 = Wx[(size_t)j * DIN + (k2-512)]; v1 = Wx[(size_t)j * DIN + (k2-512) + 1]; }
    __half2 h = __floats2half2_rn(v0, v1);
    g_Wf[i] = *reinterpret_cast<uint32_t*>(&h);
}

// ---- prep: x -> A fragments (one-time) ----
__global__ void prep_x(const float* __restrict__ x) {
    size_t i = (size_t)blockIdx.x * blockDim.x + threadIdx.x;  // 8,388,608 lane-entries
    int lane = (int)(i & 31);
    int mt   = (int)((i >> 5) & 1);
    int kt   = (int)((i >> 6) & 7);
    int t    = (int)((i >> 9) & 1023);
    int g    = (int)(i >> 19);
    int r = mt * 16 + (lane >> 2);
    int k = kt * 16 + 2 * (lane & 3);
    uint32_t w[4];
    #pragma unroll
    for (int a = 0; a < 4; ++a) {
        int i_hi = a >> 1, i_r8 = a & 1;
        int b  = g * 32 + r + 8 * i_r8;
        int kk = k + 8 * i_hi;
        const float* p = &x[((size_t)b * TT + t) * DIN + kk];
        __half2 h = __floats2half2_rn(p[0], p[1]);
        w[a] = *reinterpret_cast<uint32_t*>(&h);
    }
    *reinterpret_cast<uint4*>(&g_xf[i * 4]) = make_uint4(w[0], w[1], w[2], w[3]);
}

__global__ void zero_kernel() {
    int i = blockIdx.x * blockDim.x + threadIdx.x;
    int stride = gridDim.x * blockDim.x;
    for (int k = i; k < NG * 32 * 2 * 32 * 4; k += stride) g_hf[0][k] = 0u;
    unsigned* f = &g_flag[0][0][0];
    for (int k = i; k < NG * NS * 32; k += stride) f[k] = 0u;
}

#define MMA(AC, A0, A1, A2, A3, B0, B1)                                        \
    asm volatile(                                                              \
        "mma.sync.aligned.m16n8k16.row.col.f32.f16.f16.f32 "                   \
        "{%0,%1,%2,%3}, {%4,%5,%6,%7}, {%8,%9}, {%0,%1,%2,%3};"                \
        : "+f"((AC)[0]), "+f"((AC)[1]), "+f"((AC)[2]), "+f"((AC)[3])           \
        : "r"(A0), "r"(A1), "r"(A2), "r"(A3), "r"(B0), "r"(B1))

#define LDS128(R0, R1, R2, R3, ADDR)                                           \
    asm volatile("ld.shared.v4.u32 {%0,%1,%2,%3}, [%4];"                       \
        : "=r"(R0), "=r"(R1), "=r"(R2), "=r"(R3) : "r"(ADDR))

__global__ __launch_bounds__(NTHR, 1) void scan_kernel(
    const float* __restrict__ bx,
    const float* __restrict__ bh)
{
    extern __shared__ char smem[];
    const uint32_t sb = (uint32_t)__cvta_generic_to_shared(smem);
    float* bias_s = reinterpret_cast<float*>(smem + SM_BIAS);

    const int tid  = threadIdx.x;
    const int lane = tid & 31;
    const int wid  = tid >> 5;
    const int g    = blockIdx.x >> 3;
    const int s    = blockIdx.x & 7;
    const int mt_w = wid & 1;            // warp's m-tile (0/1)
    const int ng   = wid >> 1;           // warp's n-pair (0..3) -> nt {2ng, 2ng+1}

    // ---- load W fragments, repacked ng-paired: [kt][ng][lane][b0..b3] ----
    {
        const uint2* src = reinterpret_cast<const uint2*>(g_Wf);
        uint4* dst = reinterpret_cast<uint4*>(smem + SM_W);
        for (int i = tid; i < 40 * 4 * 32; i += NTHR) {
            int ln = i & 31, gg = (i >> 5) & 3, kt = i >> 7;
            uint2 a = src[(size_t)(kt * 64 + s * 8 + 2 * gg) * 32 + ln];
            uint2 b = src[(size_t)(kt * 64 + s * 8 + 2 * gg + 1) * 32 + ln];
            dst[i] = make_uint4(a.x, a.y, b.x, b.y);
        }
    }
    if (tid < 64) bias_s[tid] = bx[s * 64 + tid] + bh[s * 64 + tid];
    // zero A buffer 0 (own-slice region must read as h=0 at t=0)
    {
        uint4* d = reinterpret_cast<uint4*>(smem + SM_A);
        #pragma unroll
        for (int i = 0; i < 8; ++i)
            d[tid + 256 * i] = make_uint4(0u, 0u, 0u, 0u);
    }
    __syncthreads();

    // x fragments in registers: warp's mt, kt 0..7
    uint4 xr[8];
    #pragma unroll
    for (int kt = 0; kt < 8; ++kt)
        xr[kt] = __ldg(reinterpret_cast<const uint4*>(g_xf) +
                       (size_t)((((g * TT + 0) * 8 + kt) * 2 + mt_w) * 32 + lane));

    const uint32_t abase0 = sb + SM_A + mt_w * 512 + lane * 16;
    const uint32_t bbase  = sb + SM_W + ng * 512 + lane * 16;
    const int kt_own = s * 4;            // this CTA's own 4 h-kts

    for (int t = 0; t < TT; ++t) {
        const int pr = t & 1, pw = pr ^ 1;
        const uint32_t abase = abase0 + pr * 32768;
        float a0A[4] = {0,0,0,0}, a0B[4] = {0,0,0,0};
        float a1A[4] = {0,0,0,0}, a1B[4] = {0,0,0,0};

        // ---- pre-wait: x MMAs from registers (B kt 32..39) ----
        #pragma unroll
        for (int kt = 0; kt < 8; ++kt) {
            uint32_t b0, b1, b2, b3;
            LDS128(b0, b1, b2, b3, bbase + (32 + kt) * 2048);
            float* c0 = (kt & 1) ? a0B : a0A;
            float* c1 = (kt & 1) ? a1B : a1A;
            MMA(c0, xr[kt].x, xr[kt].y, xr[kt].z, xr[kt].w, b0, b1);
            MMA(c1, xr[kt].x, xr[kt].y, xr[kt].z, xr[kt].w, b2, b3);
        }
        // ---- pre-wait: own-slice h MMAs (kt_own..+3, from smem buf[pr]) ----
        #pragma unroll
        for (int i = 0; i < 4; ++i) {
            const int kt = kt_own + i;
            uint32_t A0, A1, A2, A3, b0, b1, b2, b3;
            LDS128(A0, A1, A2, A3, abase + kt * 1024);
            LDS128(b0, b1, b2, b3, bbase + kt * 2048);
            float* c0 = (i & 1) ? a0B : a0A;
            float* c1 = (i & 1) ? a1B : a1A;
            MMA(c0, A0, A1, A2, A3, b0, b1);
            MMA(c1, A0, A1, A2, A3, b2, b3);
        }
        // prefetch x(t+1) into regs
        {
            const int tn = (t + 1 < TT) ? t + 1 : TT - 1;
            #pragma unroll
            for (int kt = 0; kt < 8; ++kt)
                xr[kt] = __ldg(reinterpret_cast<const uint4*>(g_xf) +
                               (size_t)((((g * TT + tn) * 8 + kt) * 2 + mt_w) * 32 + lane));
        }

        // ---- wait peers: h_t published ----
        if (tid < NS) {
            unsigned v;
            do {
                asm volatile("ld.acquire.gpu.global.u32 %0, [%1];"
                             : "=r"(v) : "l"(&g_flag[g][tid][0]));
            } while (v < (unsigned)t);
        }
        __syncthreads();

        // ---- single-shot h stage into buf[pr]: 32 KB, MLP 8 ----
        {
            uint4 pre[8];
            const uint4* src = reinterpret_cast<const uint4*>(&g_hf[pr][0]);
            #pragma unroll
            for (int hc = 0; hc < 4; ++hc) {
                pre[2 * hc]     = __ldcg(src + (size_t)(g * 32 + hc * 8) * 64 + tid * 2);
                pre[2 * hc + 1] = __ldcg(src + (size_t)(g * 32 + hc * 8) * 64 + tid * 2 + 1);
            }
            #pragma unroll
            for (int hc = 0; hc < 4; ++hc) {
                uint4* d = reinterpret_cast<uint4*>(smem + SM_A + pr * 32768 + hc * 8192);
                d[tid * 2]     = pre[2 * hc];
                d[tid * 2 + 1] = pre[2 * hc + 1];
            }
        }
        __syncthreads();

        // ---- h MMAs: 28 kt (own slice already done pre-wait) ----
        #pragma unroll
        for (int kt = 0; kt < 32; ++kt) {
            if ((kt >> 2) == s) continue;
            uint32_t A0, A1, A2, A3, b0, b1, b2, b3;
            LDS128(A0, A1, A2, A3, abase + kt * 1024);
            LDS128(b0, b1, b2, b3, bbase + kt * 2048);
            float* c0 = (kt & 1) ? a0B : a0A;
            float* c1 = (kt & 1) ? a1B : a1A;
            MMA(c0, A0, A1, A2, A3, b0, b1);
            MMA(c1, A0, A1, A2, A3, b2, b3);
        }

        // merge banks
        float acc0[4], acc1[4];
        #pragma unroll
        for (int i = 0; i < 4; ++i) { acc0[i] = a0A[i] + a0B[i]; acc1[i] = a1A[i] + a1B[i]; }

        // ---- epilogue: bias + tanh, pack fp16x2, publish global + mirror smem ----
        {
            uint32_t* hdst = &g_hf[pw][0];
            char* sdst = smem + SM_A + pw * 32768;
            #pragma unroll
            for (int tile = 0; tile < 2; ++tile) {
                const float* ac = tile ? acc1 : acc0;
                const int ntl = 2 * ng + tile;
                const int jl  = ntl * 8 + 2 * (lane & 3);
                const float bf0 = bias_s[jl], bf1 = bias_s[jl + 1];
                const int kt = s * 4 + (ntl >> 1);
                #pragma unroll
                for (int ir = 0; ir < 2; ++ir) {
                    float h0 = tanhf(ac[2 * ir + 0] + bf0);
                    float h1 = tanhf(ac[2 * ir + 1] + bf1);
                    __half2 hh = __floats2half2_rn(h0, h1);
                    uint32_t word = *reinterpret_cast<uint32_t*>(&hh);
                    int a = 2 * (ntl & 1) + ir;
                    __stcg(&hdst[((g * 32 + kt) * 2 + mt_w) * 128 + lane * 4 + a], word);
                    *reinterpret_cast<uint32_t*>(
                        sdst + kt * 1024 + mt_w * 512 + lane * 16 + a * 4) = word;
                }
            }
        }

        // ---- cross-CTA step barrier (R8-proven) ----
        __syncthreads();
        if (tid == 0) {
            asm volatile("fence.acq_rel.gpu;" ::: "memory");
            asm volatile("st.release.gpu.global.u32 [%0], %1;"
                         :: "l"(&g_flag[g][s][0]), "r"((unsigned)(t + 1))
                         : "memory");
        }
    }
}

// y[b][o] = by[o] + sum_k h_T[b][k] * Wy[o][k] ; h_T fragments in g_hf[0]
__global__ __launch_bounds__(128, 1) void y_kernel(
    const float* __restrict__ Wy,
    const float* __restrict__ by,
    float* __restrict__ y)
{
    __shared__ float hs[HH];
    const int b = blockIdx.x, o = threadIdx.x;
    const int g = b >> 5, m = b & 31, mt = m >> 4;
    const uint32_t* hf = &g_hf[0][0];
    #pragma unroll
    for (int w = 0; w < 2; ++w) {
        int k  = o * 4 + w * 2;
        int kt = k >> 4, kl = k & 15;
        int lane = ((m & 7) << 2) | ((kl & 7) >> 1);
        int a = 2 * (kl >> 3) + ((m >> 3) & 1);
        uint32_t word = hf[((g * 32 + kt) * 2 + mt) * 128 + lane * 4 + a];
        __half2 hh = *reinterpret_cast<__half2*>(&word);
        hs[k]     = __low2float(hh);
        hs[k + 1] = __high2float(hh);
    }
    __syncthreads();
    const float4* w4 = reinterpret_cast<const float4*>(&Wy[(size_t)o * HH]);
    float acc = by[o];
    #pragma unroll 8
    for (int q = 0; q < HH / 4; ++q) {
        float4 w = __ldg(&w4[q]);
        acc = fmaf(w.x, hs[4 * q + 0], acc);
        acc = fmaf(w.y, hs[4 * q + 1], acc);
        acc = fmaf(w.z, hs[4 * q + 2], acc);
        acc = fmaf(w.w, hs[4 * q + 3], acc);
    }
    y[(size_t)b * DOUT + o] = acc;
}

extern "C" void kernel_launch(void* const* d_in, const int* in_sizes, int n_in,
                              void* d_out, int out_size) {
    const float* x  = (const float*)d_in[0];
    const float* Wx = (const float*)d_in[1];
    const float* bx = (const float*)d_in[2];
    const float* Wh = (const float*)d_in[3];
    const float* bh = (const float*)d_in[4];
    const float* Wy = (const float*)d_in[5];
    const float* by = (const float*)d_in[6];
    float* y = (float*)d_out;

    cudaFuncSetAttribute(scan_kernel,
                         cudaFuncAttributeMaxDynamicSharedMemorySize, SMEM_TOTAL);

    prep_w<<<640, 256>>>(Wh, Wx);
    prep_x<<<32768, 256>>>(x);
    zero_kernel<<<128, 256>>>();
    scan_kernel<<<NG * NS, NTHR, SMEM_TOTAL>>>(bx, bh);
    y_kernel<<<512, 128>>>(Wy, by, y);
}

// round 17
// speedup vs baseline: 1.5798x; 1.0399x over previous
#include <cuda_runtime.h>
#include <cuda_fp16.h>
#include <math.h>
#include <stdint.h>

#define TT   1024
#define DIN  128
#define HH   512
#define DOUT 128
#define NG   16
#define NS   8
#define NTHR 256

// smem byte offsets
#define SM_W   0                        // [40 kt][4 ng][32 lane][16B] = 81920 B
#define SM_A   81920                    // 2 streams x [32 kt][32 lane][16B] = 32768 B
#define SM_BIAS (SM_A + 32768)          // 64 floats
#define SMEM_TOTAL (SM_BIAS + 256)

// fragment-order fp16 globals
__device__ uint32_t g_Wf[40 * 64 * 32 * 2];                    // B frags (W), 640KB
__device__ uint32_t g_xf[(size_t)NG * TT * 8 * 2 * 32 * 4];    // A frags (x), 128MB
__device__ uint32_t g_hf[2][NG * 32 * 2 * 32 * 4];             // A frags (h), 2x512KB
__device__ unsigned g_flag[NG][NS][2][32];                     // per-stream flags

// ---- prep: W -> B fragments.  B[k][n] = W[j=n][k] ----
__global__ void prep_w(const float* __restrict__ Wh, const float* __restrict__ Wx) {
    int i = blockIdx.x * blockDim.x + threadIdx.x;   // one b32 (2 fp16)
    if (i >= 40 * 64 * 32 * 2) return;
    int breg = i & 1;
    int lane = (i >> 1) & 31;
    int nt   = (i >> 6) & 63;
    int kt   = i >> 12;                  // 0..39 (0..31 = Wh, 32..39 = Wx)
    int j  = nt * 8 + (lane >> 2);
    int k2 = kt * 16 + 2 * (lane & 3) + 8 * breg;
    float v0, v1;
    if (kt < 32) { v0 = Wh[(size_t)j * HH + k2];        v1 = Wh[(size_t)j * HH + k2 + 1]; }
    else         { v0 = Wx[(size_t)j * DIN + (k2-512)]; v1 = Wx[(size_t)j * DIN + (k2-512) + 1]; }
    __half2 h = __floats2half2_rn(v0, v1);
    g_Wf[i] = *reinterpret_cast<uint32_t*>(&h);
}

// ---- prep: x -> A fragments (one-time) ----
__global__ void prep_x(const float* __restrict__ x) {
    size_t i = (size_t)blockIdx.x * blockDim.x + threadIdx.x;  // 8,388,608 lane-entries
    int lane = (int)(i & 31);
    int mt   = (int)((i >> 5) & 1);
    int kt   = (int)((i >> 6) & 7);
    int t    = (int)((i >> 9) & 1023);
    int g    = (int)(i >> 19);
    int r = mt * 16 + (lane >> 2);
    int k = kt * 16 + 2 * (lane & 3);
    uint32_t w[4];
    #pragma unroll
    for (int a = 0; a < 4; ++a) {
        int i_hi = a >> 1, i_r8 = a & 1;
        int b  = g * 32 + r + 8 * i_r8;
        int kk = k + 8 * i_hi;
        const float* p = &x[((size_t)b * TT + t) * DIN + kk];
        __half2 h = __floats2half2_rn(p[0], p[1]);
        w[a] = *reinterpret_cast<uint32_t*>(&h);
    }
    *reinterpret_cast<uint4*>(&g_xf[i * 4]) = make_uint4(w[0], w[1], w[2], w[3]);
}

__global__ void zero_kernel() {
    int i = blockIdx.x * blockDim.x + threadIdx.x;
    int stride = gridDim.x * blockDim.x;
    for (int k = i; k < NG * 32 * 2 * 32 * 4; k += stride) g_hf[0][k] = 0u;
    unsigned* f = &g_flag[0][0][0][0];
    for (int k = i; k < NG * NS * 2 * 32; k += stride) f[k] = 0u;
}

#define MMA(AC, A0, A1, A2, A3, B0, B1)                                        \
    asm volatile(                                                              \
        "mma.sync.aligned.m16n8k16.row.col.f32.f16.f16.f32 "                   \
        "{%0,%1,%2,%3}, {%4,%5,%6,%7}, {%8,%9}, {%0,%1,%2,%3};"                \
        : "+f"((AC)[0]), "+f"((AC)[1]), "+f"((AC)[2]), "+f"((AC)[3])           \
        : "r"(A0), "r"(A1), "r"(A2), "r"(A3), "r"(B0), "r"(B1))

#define LDS128(R0, R1, R2, R3, ADDR)                                           \
    asm volatile("ld.shared.v4.u32 {%0,%1,%2,%3}, [%4];"                       \
        : "=r"(R0), "=r"(R1), "=r"(R2), "=r"(R3) : "r"(ADDR))

#define SBAR(ID)                                                               \
    asm volatile("bar.sync %0, 128;" :: "r"(ID) : "memory")

__global__ __launch_bounds__(NTHR, 1) void scan_kernel(
    const float* __restrict__ bx,
    const float* __restrict__ bh)
{
    extern __shared__ char smem[];
    const uint32_t sb = (uint32_t)__cvta_generic_to_shared(smem);
    float* bias_s = reinterpret_cast<float*>(smem + SM_BIAS);

    const int tid  = threadIdx.x;
    const int lane = tid & 31;
    const int g    = blockIdx.x >> 3;
    const int s    = blockIdx.x & 7;
    const int hf_s = tid >> 7;           // stream 0/1 (= m-tile)
    const int wtid = tid & 127;          // tid within stream
    const int ng   = wtid >> 5;          // warp-in-stream = n-pair (0..3)
    const int barid = 1 + hf_s;

    // ---- load W fragments, repacked ng-paired: [kt][ng][lane][b0..b3] ----
    {
        const uint2* src = reinterpret_cast<const uint2*>(g_Wf);
        uint4* dst = reinterpret_cast<uint4*>(smem + SM_W);
        for (int i = tid; i < 40 * 4 * 32; i += NTHR) {
            int ln = i & 31, gg = (i >> 5) & 3, kt = i >> 7;
            uint2 a = src[(size_t)(kt * 64 + s * 8 + 2 * gg) * 32 + ln];
            uint2 b = src[(size_t)(kt * 64 + s * 8 + 2 * gg + 1) * 32 + ln];
            dst[i] = make_uint4(a.x, a.y, b.x, b.y);
        }
    }
    if (tid < 64) bias_s[tid] = bx[s * 64 + tid] + bh[s * 64 + tid];
    __syncthreads();

    // x fragments in registers: stream's m-tile, kt 0..7
    uint4 xr[8];
    #pragma unroll
    for (int kt = 0; kt < 8; ++kt)
        xr[kt] = __ldg(reinterpret_cast<const uint4*>(g_xf) +
                       (size_t)((((g * TT + 0) * 8 + kt) * 2 + hf_s) * 32 + lane));

    const uint32_t abase = sb + SM_A + hf_s * 16384 + lane * 16;
    const uint32_t bbase = sb + SM_W + ng * 512 + lane * 16;
    // h fragment source/dest base for this (g, stream): uint4 index
    const uint4* hsrc0 = reinterpret_cast<const uint4*>(&g_hf[0][0]);
    const uint4* hsrc1 = reinterpret_cast<const uint4*>(&g_hf[1][0]);

    for (int t = 0; t < TT; ++t) {
        const int pr = t & 1, pw = pr ^ 1;
        float acc0[4] = {0.f, 0.f, 0.f, 0.f};
        float acc1[4] = {0.f, 0.f, 0.f, 0.f};

        // ---- pre-wait: x MMAs from registers (B kt 32..39) ----
        #pragma unroll
        for (int kt = 0; kt < 8; ++kt) {
            uint32_t b0, b1, b2, b3;
            LDS128(b0, b1, b2, b3, bbase + (32 + kt) * 2048);
            MMA(acc0, xr[kt].x, xr[kt].y, xr[kt].z, xr[kt].w, b0, b1);
            MMA(acc1, xr[kt].x, xr[kt].y, xr[kt].z, xr[kt].w, b2, b3);
        }
        // prefetch x(t+1)
        {
            const int tn = (t + 1 < TT) ? t + 1 : TT - 1;
            #pragma unroll
            for (int kt = 0; kt < 8; ++kt)
                xr[kt] = __ldg(reinterpret_cast<const uint4*>(g_xf) +
                               (size_t)((((g * TT + tn) * 8 + kt) * 2 + hf_s) * 32 + lane));
        }

        // ---- wait peers of THIS stream ----
        if (wtid < NS) {
            unsigned v;
            do {
                asm volatile("ld.acquire.gpu.global.u32 %0, [%1];"
                             : "=r"(v) : "l"(&g_flag[g][wtid][hf_s][0]));
            } while (v < (unsigned)t);
        }
        SBAR(barid);

        // ---- stage this stream's h: 16 KB (32 kt x 512 B), MLP 8 ----
        {
            const uint4* src = pr ? hsrc1 : hsrc0;
            uint4 pre[8];
            #pragma unroll
            for (int q = 0; q < 8; ++q) {
                int idx = q * 128 + wtid;            // 0..1023
                int kt = idx >> 5, off = idx & 31;
                pre[q] = __ldcg(src + (size_t)((g * 32 + kt) * 2 + hf_s) * 32 + off);
            }
            uint4* dst = reinterpret_cast<uint4*>(smem + SM_A + hf_s * 16384);
            #pragma unroll
            for (int q = 0; q < 8; ++q)
                dst[q * 128 + wtid] = pre[q];
        }
        SBAR(barid);

        // ---- h MMAs: 32 kt ----
        #pragma unroll
        for (int kt = 0; kt < 32; ++kt) {
            uint32_t A0, A1, A2, A3, b0, b1, b2, b3;
            LDS128(A0, A1, A2, A3, abase + kt * 512);
            LDS128(b0, b1, b2, b3, bbase + kt * 2048);
            MMA(acc0, A0, A1, A2, A3, b0, b1);
            MMA(acc1, A0, A1, A2, A3, b2, b3);
        }

        // ---- epilogue: bias + tanh, pack fp16x2, publish fragment layout ----
        {
            uint32_t* hdst = &g_hf[pw][0];
            #pragma unroll
            for (int tile = 0; tile < 2; ++tile) {
                const float* ac = tile ? acc1 : acc0;
                const int ntl = 2 * ng + tile;
                const int jl  = ntl * 8 + 2 * (lane & 3);
                const float bf0 = bias_s[jl], bf1 = bias_s[jl + 1];
                const int kt = s * 4 + (ntl >> 1);
                #pragma unroll
                for (int ir = 0; ir < 2; ++ir) {
                    float h0 = tanhf(ac[2 * ir + 0] + bf0);
                    float h1 = tanhf(ac[2 * ir + 1] + bf1);
                    __half2 hh = __floats2half2_rn(h0, h1);
                    int a = 2 * (ntl & 1) + ir;
                    __stcg(&hdst[((g * 32 + kt) * 2 + hf_s) * 128 + lane * 4 + a],
                           *reinterpret_cast<uint32_t*>(&hh));
                }
            }
        }

        // ---- per-stream release ----
        SBAR(barid);
        if (wtid == 0) {
            asm volatile("fence.acq_rel.gpu;" ::: "memory");
            asm volatile("st.release.gpu.global.u32 [%0], %1;"
                         :: "l"(&g_flag[g][s][hf_s][0]), "r"((unsigned)(t + 1))
                         : "memory");
        }
    }
}

// y[b][o] = by[o] + sum_k h_T[b][k] * Wy[o][k] ; h_T fragments in g_hf[0]
__global__ __launch_bounds__(128, 1) void y_kernel(
    const float* __restrict__ Wy,
    const float* __restrict__ by,
    float* __restrict__ y)
{
    __shared__ float hs[HH];
    const int b = blockIdx.x, o = threadIdx.x;
    const int g = b >> 5, m = b & 31, mt = m >> 4;
    const uint32_t* hf = &g_hf[0][0];
    #pragma unroll
    for (int w = 0; w < 2; ++w) {
        int k  = o * 4 + w * 2;
        int kt = k >> 4, kl = k & 15;
        int lane = ((m & 7) << 2) | ((kl & 7) >> 1);
        int a = 2 * (kl >> 3) + ((m >> 3) & 1);
        uint32_t word = hf[((g * 32 + kt) * 2 + mt) * 128 + lane * 4 + a];
        __half2 hh = *reinterpret_cast<__half2*>(&word);
        hs[k]     = __low2float(hh);
        hs[k + 1] = __high2float(hh);
    }
    __syncthreads();
    const float4* w4 = reinterpret_cast<const float4*>(&Wy[(size_t)o * HH]);
    float acc = by[o];
    #pragma unroll 8
    for (int q = 0; q < HH / 4; ++q) {
        float4 w = __ldg(&w4[q]);
        acc = fmaf(w.x, hs[4 * q + 0], acc);
        acc = fmaf(w.y, hs[4 * q + 1], acc);
        acc = fmaf(w.z, hs[4 * q + 2], acc);
        acc = fmaf(w.w, hs[4 * q + 3], acc);
    }
    y[(size_t)b * DOUT + o] = acc;
}

extern "C" void kernel_launch(void* const* d_in, const int* in_sizes, int n_in,
                              void* d_out, int out_size) {
    const float* x  = (const float*)d_in[0];
    const float* Wx = (const float*)d_in[1];
    const float* bx = (const float*)d_in[2];
    const float* Wh = (const float*)d_in[3];
    const float* bh = (const float*)d_in[4];
    const float* Wy = (const float*)d_in[5];
    const float* by = (const float*)d_in[6];
    float* y = (float*)d_out;

    cudaFuncSetAttribute(scan_kernel,
                         cudaFuncAttributeMaxDynamicSharedMemorySize, SMEM_TOTAL);

    prep_w<<<640, 256>>>(Wh, Wx);
    prep_x<<<32768, 256>>>(x);
    zero_kernel<<<128, 256>>>();
    scan_kernel<<<NG * NS, NTHR, SMEM_TOTAL>>>(bx, bh);
    y_kernel<<<512, 128>>>(Wy, by, y);
}